// round 6
// baseline (speedup 1.0000x reference)
#include <cuda_runtime.h>
#include <float.h>

#define D      8192
#define D4     2048          // D / 4 (float4 per row)
#define GAMMA  0.95f
#define NSLAB  148           // one row-slab per SM-column of the balanced grid
#define CTILE  8             // column tiles (CTILE * 1024 = D)

// ---------------- device scratch (no allocations allowed) ----------------
__device__ float g_part_dot[NSLAB][D];   // fully rewritten every call
__device__ float g_part_sq [NSLAB][D];
__device__ float g_dot[D];
__device__ float g_sq [D];
__device__ float g_wr  [D];              // w_r with column min_idx zeroed
__device__ float g_addk[D];              // w_u_new * k (per column add for mk)
__device__ float g_addu[D];              // w_w_new * u (per column add for mu)
__device__ int   g_min_idx;

// output layout (element offsets into d_out, float32)
#define OFF_UF  ((size_t)0)
#define OFF_MK  ((size_t)D)
#define OFF_MU  ((size_t)D + (size_t)D * D)
#define OFF_WW  ((size_t)D + 2ull * (size_t)D * D)
#define OFF_WU  (OFF_WW + (size_t)D)
#define OFF_WLU (OFF_WU + (size_t)D)

// ---------------- kernel 1: partial column reductions over mk ----------------
// grid 1184 = CTILE(8) x NSLAB(148) -> exactly 8 blocks per SM, one balanced
// wave. Block handles columns [ct*1024, +1024) x rows [s*D/148, (s+1)*D/148)
// (55 or 56 rows).
__global__ __launch_bounds__(256) void k1_colred(const float* __restrict__ mk,
                                                 const float* __restrict__ kvec)
{
    __shared__ float sk[56];
    const int bid = blockIdx.x;
    const int ct  = bid & 7;
    const int s   = bid >> 3;
    const int tid = threadIdx.x;
    const int row0 = (s * D) / NSLAB;
    const int row1 = ((s + 1) * D) / NSLAB;
    const int nr   = row1 - row0;

    if (tid < nr) sk[tid] = kvec[row0 + tid];
    __syncthreads();

    const int col4 = ct * 256 + tid;   // float4 column index within row
    const float4* __restrict__ mk4 = (const float4*)mk + (size_t)row0 * D4 + col4;

    float4 ad = make_float4(0.f, 0.f, 0.f, 0.f);
    float4 as = make_float4(0.f, 0.f, 0.f, 0.f);

    int r = 0;
    for (; r + 8 <= nr; r += 8) {
        float4 v[8];
#pragma unroll
        for (int i = 0; i < 8; ++i)
            v[i] = mk4[(size_t)(r + i) * D4];
#pragma unroll
        for (int i = 0; i < 8; ++i) {
            float kr = sk[r + i];
            ad.x += kr * v[i].x; ad.y += kr * v[i].y;
            ad.z += kr * v[i].z; ad.w += kr * v[i].w;
            as.x += v[i].x * v[i].x; as.y += v[i].y * v[i].y;
            as.z += v[i].z * v[i].z; as.w += v[i].w * v[i].w;
        }
    }
    for (; r < nr; ++r) {
        float4 v = mk4[(size_t)r * D4];
        float kr = sk[r];
        ad.x += kr * v.x; ad.y += kr * v.y; ad.z += kr * v.z; ad.w += kr * v.w;
        as.x += v.x * v.x; as.y += v.y * v.y; as.z += v.z * v.z; as.w += v.w * v.w;
    }

    ((float4*)g_part_dot[s])[col4] = ad;
    ((float4*)g_part_sq [s])[col4] = as;
}

// ---------------- kernel 1b: deterministic slab reduction ----------------
__global__ __launch_bounds__(512) void k1b_reduce()
{
    const int j = blockIdx.x * 512 + threadIdx.x;
    float sd = 0.f, ss = 0.f;
#pragma unroll 4
    for (int s = 0; s < NSLAB; ++s) {
        sd += g_part_dot[s][j];
        ss += g_part_sq [s][j];
    }
    g_dot[j] = sd;
    g_sq [j] = ss;
}

// ---------------- warp helpers ----------------
__device__ __forceinline__ float warp_sum(float v) {
#pragma unroll
    for (int o = 16; o > 0; o >>= 1) v += __shfl_xor_sync(0xffffffffu, v, o);
    return v;
}
__device__ __forceinline__ float warp_max(float v) {
#pragma unroll
    for (int o = 16; o > 0; o >>= 1) v = fmaxf(v, __shfl_xor_sync(0xffffffffu, v, o));
    return v;
}
__device__ __forceinline__ float warp_min(float v) {
#pragma unroll
    for (int o = 16; o > 0; o >>= 1) v = fminf(v, __shfl_xor_sync(0xffffffffu, v, o));
    return v;
}

// ---------------- kernel 2: the whole vector epilogue (1 block, 1024 thr) ----
__global__ __launch_bounds__(1024) void k2_vec(const float* __restrict__ kvec,
                                               const float* __restrict__ uvec,
                                               const float* __restrict__ w_w,
                                               const float* __restrict__ w_u,
                                               const float* __restrict__ w_lu,
                                               const float* __restrict__ beta_p,
                                               float* __restrict__ out)
{
    const int tid  = threadIdx.x;
    const int lane = tid & 31;
    const int wid  = tid >> 5;

    __shared__ float sredf[32];
    __shared__ int   sredi[32];
    __shared__ float s_knorm, s_max, s_sum, s_min;
    __shared__ int   s_minidx;

    // ---- phase 1: ||k||^2 and first-index argmin(w_u) ----
    float kv[8];
    float ks = 0.f;
    float bestv = FLT_MAX;
    int   besti = 0x7fffffff;
#pragma unroll
    for (int p = 0; p < 8; ++p) {
        int j = tid + p * 1024;
        float kj = kvec[j];
        kv[p] = kj;
        ks += kj * kj;
        float wuj = w_u[j];
        if (wuj < bestv || (wuj == bestv && j < besti)) { bestv = wuj; besti = j; }
    }
    {
        float v = warp_sum(ks);
        if (lane == 0) sredf[wid] = v;
        __syncthreads();
        if (tid < 32) {
            float t = warp_sum(sredf[tid]);
            if (tid == 0) s_knorm = sqrtf(t);
        }
        __syncthreads();
    }
    {
#pragma unroll
        for (int o = 16; o > 0; o >>= 1) {
            float ov = __shfl_xor_sync(0xffffffffu, bestv, o);
            int   oi = __shfl_xor_sync(0xffffffffu, besti, o);
            if (ov < bestv || (ov == bestv && oi < besti)) { bestv = ov; besti = oi; }
        }
        if (lane == 0) { sredf[wid] = bestv; sredi[wid] = besti; }
        __syncthreads();
        if (tid < 32) {
            float bv = sredf[tid];
            int   bi = sredi[tid];
#pragma unroll
            for (int o = 16; o > 0; o >>= 1) {
                float ov = __shfl_xor_sync(0xffffffffu, bv, o);
                int   oi = __shfl_xor_sync(0xffffffffu, bi, o);
                if (ov < bv || (ov == bv && oi < bi)) { bv = ov; bi = oi; }
            }
            if (tid == 0) { s_minidx = bi; g_min_idx = bi; }
        }
        __syncthreads();
    }
    const float knorm  = s_knorm;
    const int   minidx = s_minidx;

    // ---- phase 2: cosine sim + max ----
    float simv[8];
    float lmax = -FLT_MAX;
#pragma unroll
    for (int p = 0; p < 8; ++p) {
        int j = tid + p * 1024;
        float s = g_dot[j] / (knorm * sqrtf(g_sq[j]));
        simv[p] = s;
        lmax = fmaxf(lmax, s);
    }
    {
        float v = warp_max(lmax);
        if (lane == 0) sredf[wid] = v;
        __syncthreads();
        if (tid < 32) {
            float t = warp_max(sredf[tid]);
            if (tid == 0) s_max = t;
        }
        __syncthreads();
    }
    const float smax = s_max;

    // ---- phase 3: exp + sum ----
    float ev[8];
    float lsum = 0.f;
#pragma unroll
    for (int p = 0; p < 8; ++p) {
        ev[p] = __expf(simv[p] - smax);
        lsum += ev[p];
    }
    {
        float v = warp_sum(lsum);
        if (lane == 0) sredf[wid] = v;
        __syncthreads();
        if (tid < 32) {
            float t = warp_sum(sredf[tid]);
            if (tid == 0) s_sum = t;
        }
        __syncthreads();
    }
    const float inv_sum = 1.f / s_sum;
    const float beta    = 1.f / (1.f + __expf(-beta_p[0]));

    // ---- phase 4: w_r, w_u_new, w_w_new, add-vectors + min(w_u_new) ----
    float wun[8];
    float lmin = FLT_MAX;
#pragma unroll
    for (int p = 0; p < 8; ++p) {
        int j = tid + p * 1024;
        float wr     = ev[p] * inv_sum;
        float wu_new = GAMMA * w_u[j] + wr + w_w[j];
        float ww_new = beta * wr + (1.f - beta) * w_lu[j];
        wun[p] = wu_new;
        lmin = fminf(lmin, wu_new);
        out[OFF_WU + j] = wu_new;
        out[OFF_WW + j] = ww_new;
        g_addk[j] = wu_new * kv[p];
        g_addu[j] = ww_new * uvec[j];
        g_wr[j]   = (j == minidx) ? 0.f : wr;   // column min_idx of mk is zeroed
    }
    {
        float v = warp_min(lmin);
        if (lane == 0) sredf[wid] = v;
        __syncthreads();
        if (tid < 32) {
            float t = warp_min(sredf[tid]);
            if (tid == 0) s_min = t;
        }
        __syncthreads();
    }
    const float minv = s_min;

    // ---- phase 5: w_lu_new (strictly-less -> faithful zeros) ----
#pragma unroll
    for (int p = 0; p < 8; ++p) {
        int j = tid + p * 1024;
        out[OFF_WLU + j] = (wun[p] < minv) ? 1.f : 0.f;
    }
}

// ---------------- kernel 3+4 fused: streaming update of mk and mu ----------
// EXACT Round-2 configuration (best measured: 174.9us): grid 2048, block 256
// (8 warps), one warp per row, no barriers, plain loads/stores, __ldg for the
// L1-resident vectors.
__global__ __launch_bounds__(256) void k34_stream(const float* __restrict__ mk,
                                                  const float* __restrict__ mu,
                                                  float* __restrict__ out)
{
    const int tid  = threadIdx.x;
    const int lane = tid & 31;
    const int wid  = tid >> 5;

    const int m   = g_min_idx;
    const int m4  = m >> 2;
    const int ml  = m & 3;

    if (blockIdx.x < 1024) {
        // ---------------- mk path ----------------
        const int row = blockIdx.x * 8 + wid;
        const float4* __restrict__ src = (const float4*)mk + (size_t)row * D4;
        float4* __restrict__ dst = (float4*)(out + OFF_MK) + (size_t)row * D4;
        const float4* __restrict__ wr4 = (const float4*)g_wr;
        const float4* __restrict__ ak4 = (const float4*)g_addk;

        float acc = 0.f;
#pragma unroll 8
        for (int it = 0; it < 64; ++it) {
            const int f = lane + (it << 5);
            float4 v = src[f];
            float4 w = __ldg(wr4 + f);
            float4 a = __ldg(ak4 + f);
            // g_wr is already zero at min_idx -> no mask needed for the dot
            acc += w.x * v.x + w.y * v.y + w.z * v.z + w.w * v.w;
            float4 o = make_float4(v.x + a.x, v.y + a.y, v.z + a.z, v.w + a.w);
            if (f == m4) {   // zeroed column: output is just the added vector
                if      (ml == 0) o.x = a.x;
                else if (ml == 1) o.y = a.y;
                else if (ml == 2) o.z = a.z;
                else              o.w = a.w;
            }
            dst[f] = o;
        }
        acc = warp_sum(acc);
        if (lane == 0) out[OFF_UF + row] = acc;
    } else {
        // ---------------- mu path ----------------
        const int row = (blockIdx.x - 1024) * 8 + wid;
        const float4* __restrict__ src = (const float4*)mu + (size_t)row * D4;
        float4* __restrict__ dst = (float4*)(out + OFF_MU) + (size_t)row * D4;
        const float4* __restrict__ au4 = (const float4*)g_addu;

#pragma unroll 8
        for (int it = 0; it < 64; ++it) {
            const int f = lane + (it << 5);
            float4 v = src[f];
            float4 a = __ldg(au4 + f);
            float4 o = make_float4(v.x + a.x, v.y + a.y, v.z + a.z, v.w + a.w);
            if (f == m4) {
                if      (ml == 0) o.x = a.x;
                else if (ml == 1) o.y = a.y;
                else if (ml == 2) o.z = a.z;
                else              o.w = a.w;
            }
            dst[f] = o;
        }
    }
}

// ---------------- launch ----------------
extern "C" void kernel_launch(void* const* d_in, const int* in_sizes, int n_in,
                              void* d_out, int out_size)
{
    const float* k_in   = (const float*)d_in[0];
    const float* u_in   = (const float*)d_in[1];
    const float* mk_in  = (const float*)d_in[2];
    const float* mu_in  = (const float*)d_in[3];
    const float* ww_in  = (const float*)d_in[4];
    const float* wu_in  = (const float*)d_in[5];
    const float* wlu_in = (const float*)d_in[6];
    const float* beta_in= (const float*)d_in[7];
    float* out = (float*)d_out;

    k1_colred<<<CTILE * NSLAB, 256>>>(mk_in, k_in);
    k1b_reduce<<<16, 512>>>();
    k2_vec<<<1, 1024>>>(k_in, u_in, ww_in, wu_in, wlu_in, beta_in, out);
    k34_stream<<<2048, 256>>>(mk_in, mu_in, out);
}

// round 7
// speedup vs baseline: 1.0700x; 1.0700x over previous
#include <cuda_runtime.h>
#include <float.h>

#define D      8192
#define D4     2048          // D / 4 (float4 per row)
#define GAMMA  0.95f
#define NSLAB  64            // row slabs in kernel 1
#define RSLAB  128           // rows per slab (NSLAB * RSLAB = D)
#define CTILE  8             // column tiles (CTILE * 1024 = D)

// ---------------- device scratch (no allocations allowed) ----------------
__device__ float g_part_dot[NSLAB][D];   // fully rewritten every call
__device__ float g_part_sq [NSLAB][D];
__device__ float g_dot[D];
__device__ float g_sq [D];
__device__ float g_wr  [D];              // w_r with column min_idx zeroed
__device__ float g_addk[D];              // w_u_new * k (per column add for mk)
__device__ float g_addu[D];              // w_w_new * u (per column add for mu)
__device__ int   g_min_idx;

// output layout (element offsets into d_out, float32)
#define OFF_UF  ((size_t)0)
#define OFF_MK  ((size_t)D)
#define OFF_MU  ((size_t)D + (size_t)D * D)
#define OFF_WW  ((size_t)D + 2ull * (size_t)D * D)
#define OFF_WU  (OFF_WW + (size_t)D)
#define OFF_WLU (OFF_WU + (size_t)D)

// ---------------- kernel 1: partial column reductions over mk ----------------
// EXACT Round-3 configuration (best measured residue): grid (8,64), block 256,
// explicit 8-deep load batching, __ldcs on the mk stream.
__global__ __launch_bounds__(256) void k1_colred(const float* __restrict__ mk,
                                                 const float* __restrict__ kvec)
{
    __shared__ float sk[RSLAB];
    const int ct  = blockIdx.x;
    const int rs  = blockIdx.y;
    const int tid = threadIdx.x;
    const int row0 = rs * RSLAB;

    if (tid < RSLAB) sk[tid] = kvec[row0 + tid];
    __syncthreads();

    const int col4 = ct * 256 + tid;   // float4 column index within row
    const float4* __restrict__ mk4 = (const float4*)mk + (size_t)row0 * D4 + col4;

    float4 ad = make_float4(0.f, 0.f, 0.f, 0.f);
    float4 as = make_float4(0.f, 0.f, 0.f, 0.f);

    for (int r = 0; r < RSLAB; r += 8) {
        float4 v[8];
#pragma unroll
        for (int i = 0; i < 8; ++i)
            v[i] = __ldcs(mk4 + (size_t)(r + i) * D4);
#pragma unroll
        for (int i = 0; i < 8; ++i) {
            float kr = sk[r + i];
            ad.x += kr * v[i].x; ad.y += kr * v[i].y;
            ad.z += kr * v[i].z; ad.w += kr * v[i].w;
            as.x += v[i].x * v[i].x; as.y += v[i].y * v[i].y;
            as.z += v[i].z * v[i].z; as.w += v[i].w * v[i].w;
        }
    }

    ((float4*)g_part_dot[rs])[col4] = ad;
    ((float4*)g_part_sq [rs])[col4] = as;
}

// ---------------- kernel 1b: deterministic slab reduction ----------------
__global__ __launch_bounds__(512) void k1b_reduce()
{
    const int j = blockIdx.x * 512 + threadIdx.x;
    float sd = 0.f, ss = 0.f;
#pragma unroll
    for (int s = 0; s < NSLAB; ++s) {
        sd += g_part_dot[s][j];
        ss += g_part_sq [s][j];
    }
    g_dot[j] = sd;
    g_sq [j] = ss;
}

// ---------------- warp helpers ----------------
__device__ __forceinline__ float warp_sum(float v) {
#pragma unroll
    for (int o = 16; o > 0; o >>= 1) v += __shfl_xor_sync(0xffffffffu, v, o);
    return v;
}
__device__ __forceinline__ float warp_max(float v) {
#pragma unroll
    for (int o = 16; o > 0; o >>= 1) v = fmaxf(v, __shfl_xor_sync(0xffffffffu, v, o));
    return v;
}
__device__ __forceinline__ float warp_min(float v) {
#pragma unroll
    for (int o = 16; o > 0; o >>= 1) v = fminf(v, __shfl_xor_sync(0xffffffffu, v, o));
    return v;
}

// ---------------- kernel 2: the whole vector epilogue (1 block, 1024 thr) ----
__global__ __launch_bounds__(1024) void k2_vec(const float* __restrict__ kvec,
                                               const float* __restrict__ uvec,
                                               const float* __restrict__ w_w,
                                               const float* __restrict__ w_u,
                                               const float* __restrict__ w_lu,
                                               const float* __restrict__ beta_p,
                                               float* __restrict__ out)
{
    const int tid  = threadIdx.x;
    const int lane = tid & 31;
    const int wid  = tid >> 5;

    __shared__ float sredf[32];
    __shared__ int   sredi[32];
    __shared__ float s_knorm, s_max, s_sum, s_min;
    __shared__ int   s_minidx;

    // ---- phase 1: ||k||^2 and first-index argmin(w_u) ----
    float kv[8];
    float ks = 0.f;
    float bestv = FLT_MAX;
    int   besti = 0x7fffffff;
#pragma unroll
    for (int p = 0; p < 8; ++p) {
        int j = tid + p * 1024;
        float kj = kvec[j];
        kv[p] = kj;
        ks += kj * kj;
        float wuj = w_u[j];
        if (wuj < bestv || (wuj == bestv && j < besti)) { bestv = wuj; besti = j; }
    }
    {
        float v = warp_sum(ks);
        if (lane == 0) sredf[wid] = v;
        __syncthreads();
        if (tid < 32) {
            float t = warp_sum(sredf[tid]);
            if (tid == 0) s_knorm = sqrtf(t);
        }
        __syncthreads();
    }
    {
#pragma unroll
        for (int o = 16; o > 0; o >>= 1) {
            float ov = __shfl_xor_sync(0xffffffffu, bestv, o);
            int   oi = __shfl_xor_sync(0xffffffffu, besti, o);
            if (ov < bestv || (ov == bestv && oi < besti)) { bestv = ov; besti = oi; }
        }
        if (lane == 0) { sredf[wid] = bestv; sredi[wid] = besti; }
        __syncthreads();
        if (tid < 32) {
            float bv = sredf[tid];
            int   bi = sredi[tid];
#pragma unroll
            for (int o = 16; o > 0; o >>= 1) {
                float ov = __shfl_xor_sync(0xffffffffu, bv, o);
                int   oi = __shfl_xor_sync(0xffffffffu, bi, o);
                if (ov < bv || (ov == bv && oi < bi)) { bv = ov; bi = oi; }
            }
            if (tid == 0) { s_minidx = bi; g_min_idx = bi; }
        }
        __syncthreads();
    }
    const float knorm  = s_knorm;
    const int   minidx = s_minidx;

    // ---- phase 2: cosine sim + max ----
    float simv[8];
    float lmax = -FLT_MAX;
#pragma unroll
    for (int p = 0; p < 8; ++p) {
        int j = tid + p * 1024;
        float s = g_dot[j] / (knorm * sqrtf(g_sq[j]));
        simv[p] = s;
        lmax = fmaxf(lmax, s);
    }
    {
        float v = warp_max(lmax);
        if (lane == 0) sredf[wid] = v;
        __syncthreads();
        if (tid < 32) {
            float t = warp_max(sredf[tid]);
            if (tid == 0) s_max = t;
        }
        __syncthreads();
    }
    const float smax = s_max;

    // ---- phase 3: exp + sum ----
    float ev[8];
    float lsum = 0.f;
#pragma unroll
    for (int p = 0; p < 8; ++p) {
        ev[p] = __expf(simv[p] - smax);
        lsum += ev[p];
    }
    {
        float v = warp_sum(lsum);
        if (lane == 0) sredf[wid] = v;
        __syncthreads();
        if (tid < 32) {
            float t = warp_sum(sredf[tid]);
            if (tid == 0) s_sum = t;
        }
        __syncthreads();
    }
    const float inv_sum = 1.f / s_sum;
    const float beta    = 1.f / (1.f + __expf(-beta_p[0]));

    // ---- phase 4: w_r, w_u_new, w_w_new, add-vectors + min(w_u_new) ----
    float wun[8];
    float lmin = FLT_MAX;
#pragma unroll
    for (int p = 0; p < 8; ++p) {
        int j = tid + p * 1024;
        float wr     = ev[p] * inv_sum;
        float wu_new = GAMMA * w_u[j] + wr + w_w[j];
        float ww_new = beta * wr + (1.f - beta) * w_lu[j];
        wun[p] = wu_new;
        lmin = fminf(lmin, wu_new);
        out[OFF_WU + j] = wu_new;
        out[OFF_WW + j] = ww_new;
        g_addk[j] = wu_new * kv[p];
        g_addu[j] = ww_new * uvec[j];
        g_wr[j]   = (j == minidx) ? 0.f : wr;   // column min_idx of mk is zeroed
    }
    {
        float v = warp_min(lmin);
        if (lane == 0) sredf[wid] = v;
        __syncthreads();
        if (tid < 32) {
            float t = warp_min(sredf[tid]);
            if (tid == 0) s_min = t;
        }
        __syncthreads();
    }
    const float minv = s_min;

    // ---- phase 5: w_lu_new (strictly-less -> faithful zeros) ----
#pragma unroll
    for (int p = 0; p < 8; ++p) {
        int j = tid + p * 1024;
        out[OFF_WLU + j] = (wun[p] < minv) ? 1.f : 0.f;
    }
}

// ---------------- kernel 3+4 fused: streaming update of mk and mu ----------
// EXACT Round-2/6 configuration (best measured: 172.4us): grid 2048, block
// 256 (8 warps), one warp per row, no barriers, plain loads/stores, __ldg for
// the L1-resident vectors. DO NOT TOUCH.
__global__ __launch_bounds__(256) void k34_stream(const float* __restrict__ mk,
                                                  const float* __restrict__ mu,
                                                  float* __restrict__ out)
{
    const int tid  = threadIdx.x;
    const int lane = tid & 31;
    const int wid  = tid >> 5;

    const int m   = g_min_idx;
    const int m4  = m >> 2;
    const int ml  = m & 3;

    if (blockIdx.x < 1024) {
        // ---------------- mk path ----------------
        const int row = blockIdx.x * 8 + wid;
        const float4* __restrict__ src = (const float4*)mk + (size_t)row * D4;
        float4* __restrict__ dst = (float4*)(out + OFF_MK) + (size_t)row * D4;
        const float4* __restrict__ wr4 = (const float4*)g_wr;
        const float4* __restrict__ ak4 = (const float4*)g_addk;

        float acc = 0.f;
#pragma unroll 8
        for (int it = 0; it < 64; ++it) {
            const int f = lane + (it << 5);
            float4 v = src[f];
            float4 w = __ldg(wr4 + f);
            float4 a = __ldg(ak4 + f);
            // g_wr is already zero at min_idx -> no mask needed for the dot
            acc += w.x * v.x + w.y * v.y + w.z * v.z + w.w * v.w;
            float4 o = make_float4(v.x + a.x, v.y + a.y, v.z + a.z, v.w + a.w);
            if (f == m4) {   // zeroed column: output is just the added vector
                if      (ml == 0) o.x = a.x;
                else if (ml == 1) o.y = a.y;
                else if (ml == 2) o.z = a.z;
                else              o.w = a.w;
            }
            dst[f] = o;
        }
        acc = warp_sum(acc);
        if (lane == 0) out[OFF_UF + row] = acc;
    } else {
        // ---------------- mu path ----------------
        const int row = (blockIdx.x - 1024) * 8 + wid;
        const float4* __restrict__ src = (const float4*)mu + (size_t)row * D4;
        float4* __restrict__ dst = (float4*)(out + OFF_MU) + (size_t)row * D4;
        const float4* __restrict__ au4 = (const float4*)g_addu;

#pragma unroll 8
        for (int it = 0; it < 64; ++it) {
            const int f = lane + (it << 5);
            float4 v = src[f];
            float4 a = __ldg(au4 + f);
            float4 o = make_float4(v.x + a.x, v.y + a.y, v.z + a.z, v.w + a.w);
            if (f == m4) {
                if      (ml == 0) o.x = a.x;
                else if (ml == 1) o.y = a.y;
                else if (ml == 2) o.z = a.z;
                else              o.w = a.w;
            }
            dst[f] = o;
        }
    }
}

// ---------------- launch ----------------
extern "C" void kernel_launch(void* const* d_in, const int* in_sizes, int n_in,
                              void* d_out, int out_size)
{
    const float* k_in   = (const float*)d_in[0];
    const float* u_in   = (const float*)d_in[1];
    const float* mk_in  = (const float*)d_in[2];
    const float* mu_in  = (const float*)d_in[3];
    const float* ww_in  = (const float*)d_in[4];
    const float* wu_in  = (const float*)d_in[5];
    const float* wlu_in = (const float*)d_in[6];
    const float* beta_in= (const float*)d_in[7];
    float* out = (float*)d_out;

    k1_colred<<<dim3(CTILE, NSLAB), 256>>>(mk_in, k_in);
    k1b_reduce<<<16, 512>>>();
    k2_vec<<<1, 1024>>>(k_in, u_in, ww_in, wu_in, wlu_in, beta_in, out);
    k34_stream<<<2048, 256>>>(mk_in, mu_in, out);
}

// round 8
// speedup vs baseline: 1.0709x; 1.0008x over previous
#include <cuda_runtime.h>
#include <float.h>

#define D      8192
#define D4     2048          // D / 4 (float4 per row)
#define GAMMA  0.95f
#define NSLAB  64            // row slabs in kernel 1
#define RSLAB  128           // rows per slab (NSLAB * RSLAB = D)
#define CTILE  8             // column tiles (CTILE * 1024 = D)

// ---------------- device scratch (no allocations allowed) ----------------
__device__ float g_part_dot[NSLAB][D];   // fully rewritten every call
__device__ float g_part_sq [NSLAB][D];
__device__ float g_dot[D];
__device__ float g_sq [D];
__device__ float g_wr  [D];              // w_r with column min_idx zeroed
__device__ float g_addk[D];              // w_u_new * k (per column add for mk)
__device__ float g_addu[D];              // w_w_new * u (per column add for mu)
__device__ int   g_min_idx;

// output layout (element offsets into d_out, float32)
#define OFF_UF  ((size_t)0)
#define OFF_MK  ((size_t)D)
#define OFF_MU  ((size_t)D + (size_t)D * D)
#define OFF_WW  ((size_t)D + 2ull * (size_t)D * D)
#define OFF_WU  (OFF_WW + (size_t)D)
#define OFF_WLU (OFF_WU + (size_t)D)

// ---------------- kernel 1: partial column reductions over mk ----------------
// EXACT Round-3 configuration (best measured): grid (8,64), block 256,
// explicit 8-deep load batching, __ldcs on the mk stream. FROZEN.
__global__ __launch_bounds__(256) void k1_colred(const float* __restrict__ mk,
                                                 const float* __restrict__ kvec)
{
    __shared__ float sk[RSLAB];
    const int ct  = blockIdx.x;
    const int rs  = blockIdx.y;
    const int tid = threadIdx.x;
    const int row0 = rs * RSLAB;

    if (tid < RSLAB) sk[tid] = kvec[row0 + tid];
    __syncthreads();

    const int col4 = ct * 256 + tid;   // float4 column index within row
    const float4* __restrict__ mk4 = (const float4*)mk + (size_t)row0 * D4 + col4;

    float4 ad = make_float4(0.f, 0.f, 0.f, 0.f);
    float4 as = make_float4(0.f, 0.f, 0.f, 0.f);

    for (int r = 0; r < RSLAB; r += 8) {
        float4 v[8];
#pragma unroll
        for (int i = 0; i < 8; ++i)
            v[i] = __ldcs(mk4 + (size_t)(r + i) * D4);
#pragma unroll
        for (int i = 0; i < 8; ++i) {
            float kr = sk[r + i];
            ad.x += kr * v[i].x; ad.y += kr * v[i].y;
            ad.z += kr * v[i].z; ad.w += kr * v[i].w;
            as.x += v[i].x * v[i].x; as.y += v[i].y * v[i].y;
            as.z += v[i].z * v[i].z; as.w += v[i].w * v[i].w;
        }
    }

    ((float4*)g_part_dot[rs])[col4] = ad;
    ((float4*)g_part_sq [rs])[col4] = as;
}

// ---------------- kernel 1b: deterministic slab reduction ----------------
// WIDENED: 64 blocks x 128 threads (same 8192 threads, 4x the SMs vs the old
// 16-block grid) so the 8MB partial read isn't bottlenecked on 16 SMs.
__global__ __launch_bounds__(128) void k1b_reduce()
{
    const int j = blockIdx.x * 128 + threadIdx.x;
    float sd = 0.f, ss = 0.f;
#pragma unroll
    for (int s = 0; s < NSLAB; ++s) {
        sd += g_part_dot[s][j];
        ss += g_part_sq [s][j];
    }
    g_dot[j] = sd;
    g_sq [j] = ss;
}

// ---------------- warp helpers ----------------
__device__ __forceinline__ float warp_sum(float v) {
#pragma unroll
    for (int o = 16; o > 0; o >>= 1) v += __shfl_xor_sync(0xffffffffu, v, o);
    return v;
}
__device__ __forceinline__ float warp_max(float v) {
#pragma unroll
    for (int o = 16; o > 0; o >>= 1) v = fmaxf(v, __shfl_xor_sync(0xffffffffu, v, o));
    return v;
}
__device__ __forceinline__ float warp_min(float v) {
#pragma unroll
    for (int o = 16; o > 0; o >>= 1) v = fminf(v, __shfl_xor_sync(0xffffffffu, v, o));
    return v;
}

// ---------------- kernel 2: the whole vector epilogue (1 block, 1024 thr) ----
__global__ __launch_bounds__(1024) void k2_vec(const float* __restrict__ kvec,
                                               const float* __restrict__ uvec,
                                               const float* __restrict__ w_w,
                                               const float* __restrict__ w_u,
                                               const float* __restrict__ w_lu,
                                               const float* __restrict__ beta_p,
                                               float* __restrict__ out)
{
    const int tid  = threadIdx.x;
    const int lane = tid & 31;
    const int wid  = tid >> 5;

    __shared__ float sredf[32];
    __shared__ int   sredi[32];
    __shared__ float s_knorm, s_max, s_sum, s_min;
    __shared__ int   s_minidx;

    // ---- phase 1: ||k||^2 and first-index argmin(w_u) ----
    float kv[8];
    float ks = 0.f;
    float bestv = FLT_MAX;
    int   besti = 0x7fffffff;
#pragma unroll
    for (int p = 0; p < 8; ++p) {
        int j = tid + p * 1024;
        float kj = kvec[j];
        kv[p] = kj;
        ks += kj * kj;
        float wuj = w_u[j];
        if (wuj < bestv || (wuj == bestv && j < besti)) { bestv = wuj; besti = j; }
    }
    {
        float v = warp_sum(ks);
        if (lane == 0) sredf[wid] = v;
        __syncthreads();
        if (tid < 32) {
            float t = warp_sum(sredf[tid]);
            if (tid == 0) s_knorm = sqrtf(t);
        }
        __syncthreads();
    }
    {
#pragma unroll
        for (int o = 16; o > 0; o >>= 1) {
            float ov = __shfl_xor_sync(0xffffffffu, bestv, o);
            int   oi = __shfl_xor_sync(0xffffffffu, besti, o);
            if (ov < bestv || (ov == bestv && oi < besti)) { bestv = ov; besti = oi; }
        }
        if (lane == 0) { sredf[wid] = bestv; sredi[wid] = besti; }
        __syncthreads();
        if (tid < 32) {
            float bv = sredf[tid];
            int   bi = sredi[tid];
#pragma unroll
            for (int o = 16; o > 0; o >>= 1) {
                float ov = __shfl_xor_sync(0xffffffffu, bv, o);
                int   oi = __shfl_xor_sync(0xffffffffu, bi, o);
                if (ov < bv || (ov == bv && oi < bi)) { bv = ov; bi = oi; }
            }
            if (tid == 0) { s_minidx = bi; g_min_idx = bi; }
        }
        __syncthreads();
    }
    const float knorm  = s_knorm;
    const int   minidx = s_minidx;

    // ---- phase 2: cosine sim + max ----
    float simv[8];
    float lmax = -FLT_MAX;
#pragma unroll
    for (int p = 0; p < 8; ++p) {
        int j = tid + p * 1024;
        float s = g_dot[j] / (knorm * sqrtf(g_sq[j]));
        simv[p] = s;
        lmax = fmaxf(lmax, s);
    }
    {
        float v = warp_max(lmax);
        if (lane == 0) sredf[wid] = v;
        __syncthreads();
        if (tid < 32) {
            float t = warp_max(sredf[tid]);
            if (tid == 0) s_max = t;
        }
        __syncthreads();
    }
    const float smax = s_max;

    // ---- phase 3: exp + sum ----
    float ev[8];
    float lsum = 0.f;
#pragma unroll
    for (int p = 0; p < 8; ++p) {
        ev[p] = __expf(simv[p] - smax);
        lsum += ev[p];
    }
    {
        float v = warp_sum(lsum);
        if (lane == 0) sredf[wid] = v;
        __syncthreads();
        if (tid < 32) {
            float t = warp_sum(sredf[tid]);
            if (tid == 0) s_sum = t;
        }
        __syncthreads();
    }
    const float inv_sum = 1.f / s_sum;
    const float beta    = 1.f / (1.f + __expf(-beta_p[0]));

    // ---- phase 4: w_r, w_u_new, w_w_new, add-vectors + min(w_u_new) ----
    float wun[8];
    float lmin = FLT_MAX;
#pragma unroll
    for (int p = 0; p < 8; ++p) {
        int j = tid + p * 1024;
        float wr     = ev[p] * inv_sum;
        float wu_new = GAMMA * w_u[j] + wr + w_w[j];
        float ww_new = beta * wr + (1.f - beta) * w_lu[j];
        wun[p] = wu_new;
        lmin = fminf(lmin, wu_new);
        out[OFF_WU + j] = wu_new;
        out[OFF_WW + j] = ww_new;
        g_addk[j] = wu_new * kv[p];
        g_addu[j] = ww_new * uvec[j];
        g_wr[j]   = (j == minidx) ? 0.f : wr;   // column min_idx of mk is zeroed
    }
    {
        float v = warp_min(lmin);
        if (lane == 0) sredf[wid] = v;
        __syncthreads();
        if (tid < 32) {
            float t = warp_min(sredf[tid]);
            if (tid == 0) s_min = t;
        }
        __syncthreads();
    }
    const float minv = s_min;

    // ---- phase 5: w_lu_new (strictly-less -> faithful zeros) ----
#pragma unroll
    for (int p = 0; p < 8; ++p) {
        int j = tid + p * 1024;
        out[OFF_WLU + j] = (wun[p] < minv) ? 1.f : 0.f;
    }
}

// ---------------- kernel 3+4 fused: streaming update of mk and mu ----------
// EXACT Round-2/6 configuration (best measured: 172.4us). FROZEN.
__global__ __launch_bounds__(256) void k34_stream(const float* __restrict__ mk,
                                                  const float* __restrict__ mu,
                                                  float* __restrict__ out)
{
    const int tid  = threadIdx.x;
    const int lane = tid & 31;
    const int wid  = tid >> 5;

    const int m   = g_min_idx;
    const int m4  = m >> 2;
    const int ml  = m & 3;

    if (blockIdx.x < 1024) {
        // ---------------- mk path ----------------
        const int row = blockIdx.x * 8 + wid;
        const float4* __restrict__ src = (const float4*)mk + (size_t)row * D4;
        float4* __restrict__ dst = (float4*)(out + OFF_MK) + (size_t)row * D4;
        const float4* __restrict__ wr4 = (const float4*)g_wr;
        const float4* __restrict__ ak4 = (const float4*)g_addk;

        float acc = 0.f;
#pragma unroll 8
        for (int it = 0; it < 64; ++it) {
            const int f = lane + (it << 5);
            float4 v = src[f];
            float4 w = __ldg(wr4 + f);
            float4 a = __ldg(ak4 + f);
            // g_wr is already zero at min_idx -> no mask needed for the dot
            acc += w.x * v.x + w.y * v.y + w.z * v.z + w.w * v.w;
            float4 o = make_float4(v.x + a.x, v.y + a.y, v.z + a.z, v.w + a.w);
            if (f == m4) {   // zeroed column: output is just the added vector
                if      (ml == 0) o.x = a.x;
                else if (ml == 1) o.y = a.y;
                else if (ml == 2) o.z = a.z;
                else              o.w = a.w;
            }
            dst[f] = o;
        }
        acc = warp_sum(acc);
        if (lane == 0) out[OFF_UF + row] = acc;
    } else {
        // ---------------- mu path ----------------
        const int row = (blockIdx.x - 1024) * 8 + wid;
        const float4* __restrict__ src = (const float4*)mu + (size_t)row * D4;
        float4* __restrict__ dst = (float4*)(out + OFF_MU) + (size_t)row * D4;
        const float4* __restrict__ au4 = (const float4*)g_addu;

#pragma unroll 8
        for (int it = 0; it < 64; ++it) {
            const int f = lane + (it << 5);
            float4 v = src[f];
            float4 a = __ldg(au4 + f);
            float4 o = make_float4(v.x + a.x, v.y + a.y, v.z + a.z, v.w + a.w);
            if (f == m4) {
                if      (ml == 0) o.x = a.x;
                else if (ml == 1) o.y = a.y;
                else if (ml == 2) o.z = a.z;
                else              o.w = a.w;
            }
            dst[f] = o;
        }
    }
}

// ---------------- launch ----------------
extern "C" void kernel_launch(void* const* d_in, const int* in_sizes, int n_in,
                              void* d_out, int out_size)
{
    const float* k_in   = (const float*)d_in[0];
    const float* u_in   = (const float*)d_in[1];
    const float* mk_in  = (const float*)d_in[2];
    const float* mu_in  = (const float*)d_in[3];
    const float* ww_in  = (const float*)d_in[4];
    const float* wu_in  = (const float*)d_in[5];
    const float* wlu_in = (const float*)d_in[6];
    const float* beta_in= (const float*)d_in[7];
    float* out = (float*)d_out;

    k1_colred<<<dim3(CTILE, NSLAB), 256>>>(mk_in, k_in);
    k1b_reduce<<<64, 128>>>();
    k2_vec<<<1, 1024>>>(k_in, u_in, ww_in, wu_in, wlu_in, beta_in, out);
    k34_stream<<<2048, 256>>>(mk_in, mu_in, out);
}